// round 1
// baseline (speedup 1.0000x reference)
#include <cuda_runtime.h>
#include <cstdint>

#define N_NODES 100000
#define F_IN    512
#define F_HID   16
#define MAX_E   3200000

// -------- device scratch (no allocations allowed) --------
__device__ int   g_is64;
__device__ int   g_src[MAX_E];
__device__ int   g_dst[MAX_E];
__device__ int   g_deg[N_NODES];
__device__ float g_dinv[N_NODES];
__device__ float g_h1[N_NODES * 16];   // x @ W1
__device__ float g_a1[N_NODES * 16];   // aggregated layer-1 (pre-bias/relu)
__device__ float g_h2[N_NODES * 8];    // relu(a1+b1) @ W2, padded to 8
__device__ float g_o2[N_NODES * 8];    // aggregated layer-2 (+b2), padded to 8

// -------- dtype detection: int64 edge_index has zero high words --------
__global__ void k_detect(const unsigned int* ei) {
    __shared__ int nz;
    if (threadIdx.x == 0) nz = 0;
    __syncthreads();
    for (int i = threadIdx.x; i < 2048; i += blockDim.x)
        if (ei[2 * i + 1] != 0u) nz = 1;
    __syncthreads();
    if (threadIdx.x == 0) g_is64 = (nz == 0) ? 1 : 0;
}

__global__ void k_initdeg() {
    int i = blockIdx.x * blockDim.x + threadIdx.x;
    if (i < N_NODES) g_deg[i] = 1;   // self-loop
}

// convert edges to int32 scratch + degree histogram (in-degree over dst)
__global__ void k_convert(const void* ei, int E) {
    int e = blockIdx.x * blockDim.x + threadIdx.x;
    if (e >= E) return;
    int s, d;
    if (g_is64) {
        const long long* p = (const long long*)ei;
        s = (int)p[e];
        d = (int)p[E + e];
    } else {
        const int* p = (const int*)ei;
        s = p[e];
        d = p[E + e];
    }
    g_src[e] = s;
    g_dst[e] = d;
    atomicAdd(&g_deg[d], 1);
}

__global__ void k_dinv() {
    int i = blockIdx.x * blockDim.x + threadIdx.x;
    if (i < N_NODES) g_dinv[i] = rsqrtf((float)g_deg[i]);
}

// -------- GEMM: h1 = x @ W1, a1 = h1 * dinv^2 (self-loop init) --------
// 256 rows per block (thread-per-row), k-chunked shared staging of x,
// inner product done with packed fma.rn.f32x2 (FFMA2).
#define KC 32
#define XS_STRIDE 36   // 32 + pad, keeps float4 alignment (144B)

__global__ void __launch_bounds__(256) k_gemm1(const float* __restrict__ x,
                                               const float* __restrict__ W1) {
    __shared__ float xs[256 * XS_STRIDE];
    __shared__ float wc[KC * 16];
    int t = threadIdx.x;
    int rbase = blockIdx.x * 256;

    unsigned long long acc[8];
#pragma unroll
    for (int j = 0; j < 8; j++) acc[j] = 0ull;

    for (int kb = 0; kb < F_IN; kb += KC) {
        __syncthreads();
        // stage x chunk: 256 rows x 32 floats, coalesced float4 loads
#pragma unroll
        for (int i = 0; i < 8; i++) {
            int flat = t + 256 * i;        // float4 index within chunk
            int row  = flat >> 3;          // 8 float4 per row
            int k4   = flat & 7;
            float4 v = make_float4(0.f, 0.f, 0.f, 0.f);
            int gr = rbase + row;
            if (gr < N_NODES)
                v = *(const float4*)(x + (size_t)gr * F_IN + kb + k4 * 4);
            *(float4*)(xs + row * XS_STRIDE + k4 * 4) = v;
        }
        // stage W chunk: 32 rows x 16 = 512 floats
        if (t < 128)
            *(float4*)(wc + t * 4) = *(const float4*)(W1 + kb * 16 + t * 4);
        __syncthreads();

#pragma unroll
        for (int k4 = 0; k4 < 8; k4++) {
            float4 xv = *(float4*)(xs + t * XS_STRIDE + k4 * 4);
            float xk[4] = {xv.x, xv.y, xv.z, xv.w};
#pragma unroll
            for (int c = 0; c < 4; c++) {
                int k = k4 * 4 + c;
                unsigned long long xx;
                asm("mov.b64 %0, {%1,%1};" : "=l"(xx) : "f"(xk[c]));
                const unsigned long long* wr =
                    (const unsigned long long*)(wc + k * 16);
#pragma unroll
                for (int j = 0; j < 8; j++)
                    asm("fma.rn.f32x2 %0, %1, %2, %0;"
                        : "+l"(acc[j]) : "l"(xx), "l"(wr[j]));
            }
        }
    }

    int r = rbase + t;
    if (r < N_NODES) {
        float di  = g_dinv[r];
        float di2 = di * di;
        float out[16];
#pragma unroll
        for (int j = 0; j < 8; j++) {
            float lo, hi;
            asm("mov.b64 {%0,%1}, %2;" : "=f"(lo), "=f"(hi) : "l"(acc[j]));
            out[2 * j]     = lo;
            out[2 * j + 1] = hi;
        }
        float4* hp = (float4*)(g_h1 + (size_t)r * 16);
        float4* ap = (float4*)(g_a1 + (size_t)r * 16);
#pragma unroll
        for (int q = 0; q < 4; q++) {
            float4 v = make_float4(out[4 * q], out[4 * q + 1],
                                   out[4 * q + 2], out[4 * q + 3]);
            hp[q] = v;
            ap[q] = make_float4(v.x * di2, v.y * di2, v.z * di2, v.w * di2);
        }
    }
}

// -------- edge aggregation layer 1: a1[d] += h1[s] * dinv[s]*dinv[d] --------
__device__ __forceinline__ void red_v4(float* addr, float a, float b, float c, float d) {
    asm volatile("red.global.add.v4.f32 [%0], {%1,%2,%3,%4};"
                 :: "l"(addr), "f"(a), "f"(b), "f"(c), "f"(d) : "memory");
}

__global__ void k_agg1(int E) {
    int e = blockIdx.x * blockDim.x + threadIdx.x;
    if (e >= E) return;
    int s = g_src[e], d = g_dst[e];
    float nrm = g_dinv[s] * g_dinv[d];
    const float4* hp = (const float4*)(g_h1 + (size_t)s * 16);
    float* ap = g_a1 + (size_t)d * 16;
#pragma unroll
    for (int q = 0; q < 4; q++) {
        float4 v = hp[q];
        red_v4(ap + 4 * q, v.x * nrm, v.y * nrm, v.z * nrm, v.w * nrm);
    }
}

// -------- layer 2 transform: h2 = relu(a1+b1) @ W2; o2 = h2*dinv^2 + b2 --------
__global__ void k_xform2(const float* __restrict__ b1,
                         const float* __restrict__ W2,
                         const float* __restrict__ b2) {
    int i = blockIdx.x * blockDim.x + threadIdx.x;
    if (i >= N_NODES) return;
    float v[16];
    const float4* ap = (const float4*)(g_a1 + (size_t)i * 16);
#pragma unroll
    for (int q = 0; q < 4; q++) {
        float4 a = ap[q];
        v[4 * q + 0] = fmaxf(a.x + __ldg(b1 + 4 * q + 0), 0.f);
        v[4 * q + 1] = fmaxf(a.y + __ldg(b1 + 4 * q + 1), 0.f);
        v[4 * q + 2] = fmaxf(a.z + __ldg(b1 + 4 * q + 2), 0.f);
        v[4 * q + 3] = fmaxf(a.w + __ldg(b1 + 4 * q + 3), 0.f);
    }
    float di  = g_dinv[i];
    float di2 = di * di;
    float h[8];
#pragma unroll
    for (int j = 0; j < 7; j++) {
        float s = 0.f;
#pragma unroll
        for (int k = 0; k < 16; k++) s += v[k] * __ldg(W2 + k * 7 + j);
        h[j] = s;
    }
    h[7] = 0.f;
    float4* hp = (float4*)(g_h2 + (size_t)i * 8);
    float4* op = (float4*)(g_o2 + (size_t)i * 8);
    hp[0] = make_float4(h[0], h[1], h[2], h[3]);
    hp[1] = make_float4(h[4], h[5], h[6], 0.f);
    op[0] = make_float4(h[0] * di2 + __ldg(b2 + 0),
                        h[1] * di2 + __ldg(b2 + 1),
                        h[2] * di2 + __ldg(b2 + 2),
                        h[3] * di2 + __ldg(b2 + 3));
    op[1] = make_float4(h[4] * di2 + __ldg(b2 + 4),
                        h[5] * di2 + __ldg(b2 + 5),
                        h[6] * di2 + __ldg(b2 + 6),
                        0.f);
}

// -------- edge aggregation layer 2: o2[d] += h2[s] * norm --------
__global__ void k_agg2(int E) {
    int e = blockIdx.x * blockDim.x + threadIdx.x;
    if (e >= E) return;
    int s = g_src[e], d = g_dst[e];
    float nrm = g_dinv[s] * g_dinv[d];
    const float4* hp = (const float4*)(g_h2 + (size_t)s * 8);
    float* op = g_o2 + (size_t)d * 8;
    float4 v0 = hp[0], v1 = hp[1];
    red_v4(op,     v0.x * nrm, v0.y * nrm, v0.z * nrm, v0.w * nrm);
    red_v4(op + 4, v1.x * nrm, v1.y * nrm, v1.z * nrm, v1.w * nrm);
}

// -------- strip padding into d_out [N,7] --------
__global__ void k_copy(float* __restrict__ out) {
    int idx = blockIdx.x * blockDim.x + threadIdx.x;
    if (idx >= N_NODES * 7) return;
    int i = idx / 7;
    int j = idx - i * 7;
    out[idx] = g_o2[i * 8 + j];
}

extern "C" void kernel_launch(void* const* d_in, const int* in_sizes, int n_in,
                              void* d_out, int out_size) {
    const float* x  = (const float*)d_in[0];
    const void*  ei = d_in[1];
    const float* W1 = (const float*)d_in[2];
    const float* b1 = (const float*)d_in[3];
    const float* W2 = (const float*)d_in[4];
    const float* b2 = (const float*)d_in[5];
    int E = in_sizes[1] / 2;

    k_detect<<<1, 256>>>((const unsigned int*)ei);
    k_initdeg<<<(N_NODES + 255) / 256, 256>>>();
    k_convert<<<(E + 255) / 256, 256>>>(ei, E);
    k_dinv<<<(N_NODES + 255) / 256, 256>>>();
    k_gemm1<<<(N_NODES + 255) / 256, 256>>>(x, W1);
    k_agg1<<<(E + 255) / 256, 256>>>(E);
    k_xform2<<<(N_NODES + 255) / 256, 256>>>(b1, W2, b2);
    k_agg2<<<(E + 255) / 256, 256>>>(E);
    k_copy<<<(N_NODES * 7 + 255) / 256, 256>>>((float*)d_out);
}